// round 1
// baseline (speedup 1.0000x reference)
#include <cuda_runtime.h>

#define BATCH 8
#define NPTS 2048
#define CIN 128
#define DQK 32
#define NSEG 8

// ---------------- scratch (device globals; no runtime allocation) ----------------
__device__ float g_q[BATCH * NPTS * DQK];
__device__ float g_k[BATCH * NPTS * DQK];
__device__ float g_v[BATCH * NPTS * CIN];
__device__ float g_E[BATCH * NPTS * NPTS];          // 134 MB energy scratch
__device__ float g_xr[BATCH * NPTS * CIN];
__device__ float g_pmax[BATCH * NPTS * NSEG];
__device__ float g_psum[BATCH * NPTS * NSEG];
__device__ float g_cmax[BATCH * NPTS];
__device__ float g_cinv[BATCH * NPTS];

// ---------------- f32x2 helpers (Blackwell packed fp32) ----------------
__device__ __forceinline__ unsigned long long pack2(float a, float b) {
    unsigned long long r;
    asm("mov.b64 %0,{%1,%2};" : "=l"(r) : "f"(a), "f"(b));
    return r;
}
__device__ __forceinline__ void unpack2(unsigned long long v, float& a, float& b) {
    asm("mov.b64 {%0,%1},%2;" : "=f"(a), "=f"(b) : "l"(v));
}
__device__ __forceinline__ unsigned long long fma2(unsigned long long a, unsigned long long b,
                                                   unsigned long long c) {
    unsigned long long d;
    asm("fma.rn.f32x2 %0,%1,%2,%3;" : "=l"(d) : "l"(a), "l"(b), "l"(c));
    return d;
}
__device__ __forceinline__ unsigned long long add2(unsigned long long a, unsigned long long b) {
    unsigned long long d;
    asm("add.rn.f32x2 %0,%1,%2;" : "=l"(d) : "l"(a), "l"(b));
    return d;
}

// ---------------- K1: q,k,v = x @ {Wq,Wk,Wv}^T  (tiled 64x64, K=128) ----------------
__global__ __launch_bounds__(256) void k_qkv(const float* __restrict__ x,
                                             const float* __restrict__ Wq,
                                             const float* __restrict__ Wk,
                                             const float* __restrict__ Wv) {
    __shared__ float As[64][33];
    __shared__ float Ws[64][33];
    const int tid = threadIdx.x;
    const int ty = tid >> 4, tx = tid & 15;
    const int r0 = blockIdx.x * 64;     // global row (b*N+n)
    const int c0 = blockIdx.y * 64;     // global col in [0,192): 0-31 q, 32-63 k, 64-191 v

    float acc[4][4] = {};
    for (int kc = 0; kc < CIN; kc += 32) {
#pragma unroll
        for (int u = 0; u < 8; u++) {
            int idx = u * 256 + tid;
            int row = idx >> 5, kk = idx & 31;
            As[row][kk] = x[(r0 + row) * CIN + kc + kk];
        }
#pragma unroll
        for (int u = 0; u < 8; u++) {
            int idx = u * 256 + tid;
            int col = idx >> 5, kk = idx & 31;
            int c = c0 + col;
            const float* wp;
            int wr;
            if (c < 32)      { wp = Wq; wr = c; }
            else if (c < 64) { wp = Wk; wr = c - 32; }
            else             { wp = Wv; wr = c - 64; }
            Ws[col][kk] = wp[wr * CIN + kc + kk];
        }
        __syncthreads();
#pragma unroll 8
        for (int kk = 0; kk < 32; kk++) {
            float a[4], bb[4];
#pragma unroll
            for (int i = 0; i < 4; i++) a[i] = As[ty * 4 + i][kk];
#pragma unroll
            for (int j = 0; j < 4; j++) bb[j] = Ws[tx * 4 + j][kk];
#pragma unroll
            for (int i = 0; i < 4; i++)
#pragma unroll
                for (int j = 0; j < 4; j++) acc[i][j] = fmaf(a[i], bb[j], acc[i][j]);
        }
        __syncthreads();
    }
#pragma unroll
    for (int i = 0; i < 4; i++) {
        int r = r0 + ty * 4 + i;
        int bb = r >> 11, n = r & (NPTS - 1);
#pragma unroll
        for (int j = 0; j < 4; j++) {
            int c = c0 + tx * 4 + j;
            float v = acc[i][j];
            if (c < 32)      g_q[(bb * NPTS + n) * DQK + c] = v;
            else if (c < 64) g_k[(bb * NPTS + n) * DQK + (c - 32)] = v;
            else             g_v[(bb * NPTS + n) * CIN + (c - 64)] = v;
        }
    }
}

// ---------------- K2: E = q @ k^T per batch (tiled 128x128, K=32) ----------------
__global__ __launch_bounds__(256) void k_energy() {
    __shared__ float Qs[128][33];
    __shared__ float Ks[128][33];
    const int tid = threadIdx.x;
    const int ty = tid >> 4, tx = tid & 15;
    const int b = blockIdx.z;
    const int n0 = blockIdx.x * 128, m0 = blockIdx.y * 128;

#pragma unroll
    for (int u = 0; u < 16; u++) {
        int idx = u * 256 + tid;
        int row = idx >> 5, kk = idx & 31;
        Qs[row][kk] = g_q[(b * NPTS + n0 + row) * DQK + kk];
        Ks[row][kk] = g_k[(b * NPTS + m0 + row) * DQK + kk];
    }
    __syncthreads();

    float acc[8][8] = {};
#pragma unroll 8
    for (int kk = 0; kk < 32; kk++) {
        float a[8], bb[8];
#pragma unroll
        for (int i = 0; i < 8; i++) a[i] = Qs[ty * 8 + i][kk];
#pragma unroll
        for (int j = 0; j < 8; j++) bb[j] = Ks[tx * 8 + j][kk];
#pragma unroll
        for (int i = 0; i < 8; i++)
#pragma unroll
            for (int j = 0; j < 8; j++) acc[i][j] = fmaf(a[i], bb[j], acc[i][j]);
    }

#pragma unroll
    for (int i = 0; i < 8; i++) {
        int row = n0 + ty * 8 + i;
        int base = (b * NPTS + row) * NPTS + m0 + tx * 8;
        float4 o0 = make_float4(acc[i][0], acc[i][1], acc[i][2], acc[i][3]);
        float4 o1 = make_float4(acc[i][4], acc[i][5], acc[i][6], acc[i][7]);
        *(float4*)&g_E[base] = o0;
        *(float4*)&g_E[base + 4] = o1;
    }
}

// ---------------- K3a: per-column (query axis) online softmax partials ----------------
__global__ __launch_bounds__(256) void k_colstats_part() {
    const int b = blockIdx.z;
    const int m = blockIdx.x * 256 + threadIdx.x;
    const int seg = blockIdx.y;
    const float* col = &g_E[b * NPTS * NPTS + m];
    const int n0 = seg * (NPTS / NSEG);
    float mx = -1e30f, s = 0.f;
    for (int n = n0; n < n0 + NPTS / NSEG; n += 8) {
        float v[8];
#pragma unroll
        for (int u = 0; u < 8; u++) v[u] = col[(n + u) * NPTS];
#pragma unroll
        for (int u = 0; u < 8; u++) {
            float vv = v[u];
            if (vv > mx) { s = s * __expf(mx - vv) + 1.f; mx = vv; }
            else         { s += __expf(vv - mx); }
        }
    }
    g_pmax[(b * NPTS + m) * NSEG + seg] = mx;
    g_psum[(b * NPTS + m) * NSEG + seg] = s;
}

// ---------------- K3b: merge partials -> cmax, 1/csum ----------------
__global__ __launch_bounds__(256) void k_colstats_merge() {
    const int idx = blockIdx.x * 256 + threadIdx.x;   // over B*N columns
    float pm[NSEG], ps[NSEG];
    float mx = -1e30f;
#pragma unroll
    for (int g = 0; g < NSEG; g++) {
        pm[g] = g_pmax[idx * NSEG + g];
        ps[g] = g_psum[idx * NSEG + g];
        mx = fmaxf(mx, pm[g]);
    }
    float s = 0.f;
#pragma unroll
    for (int g = 0; g < NSEG; g++) s += ps[g] * __expf(pm[g] - mx);
    g_cmax[idx] = mx;
    g_cinv[idx] = 1.0f / s;
}

// ---------------- K4: x_r = (P @ v) / rowsum(P);  P = exp(E-cmax)*cinv ----------------
// Dominant GEMM: per batch 2048x128x2048. f32x2 packed FMA; Vs pairs load directly packed.
__global__ __launch_bounds__(256) void k_xr() {
    __shared__ float Ps[128][33];
    __shared__ __align__(16) float Vs[32][132];
    const int tid = threadIdx.x;
    const int ty = tid >> 4, tx = tid & 15;
    const int b = blockIdx.y;
    const int n0 = blockIdx.x * 128;
    const int mm_t = tid & 31;

    unsigned long long acc[8][4];
    unsigned long long rs2[8];
#pragma unroll
    for (int i = 0; i < 8; i++) {
        rs2[i] = 0ull;
#pragma unroll
        for (int j = 0; j < 4; j++) acc[i][j] = 0ull;
    }

    for (int mc = 0; mc < NPTS; mc += 32) {
        const float cm = g_cmax[b * NPTS + mc + mm_t];
        const float ci = g_cinv[b * NPTS + mc + mm_t];
#pragma unroll
        for (int u = 0; u < 16; u++) {
            int idx = u * 256 + tid;
            int row = idx >> 5;                 // mm == mm_t
            float e = g_E[(b * NPTS + n0 + row) * NPTS + mc + mm_t];
            Ps[row][mm_t] = __expf(e - cm) * ci;
        }
#pragma unroll
        for (int u = 0; u < 16; u++) {
            int idx = u * 256 + tid;
            int mm = idx >> 7, c = idx & 127;
            Vs[mm][c] = g_v[(b * NPTS + mc + mm) * CIN + c];
        }
        __syncthreads();
#pragma unroll 4
        for (int mm = 0; mm < 32; mm++) {
            unsigned long long b2[4];
#pragma unroll
            for (int jj = 0; jj < 4; jj++)
                b2[jj] = *(const unsigned long long*)&Vs[mm][tx * 8 + jj * 2];
#pragma unroll
            for (int i = 0; i < 8; i++) {
                float p = Ps[ty * 8 + i][mm];
                unsigned long long p2 = pack2(p, p);
                rs2[i] = add2(rs2[i], p2);
#pragma unroll
                for (int jj = 0; jj < 4; jj++) acc[i][jj] = fma2(p2, b2[jj], acc[i][jj]);
            }
        }
        __syncthreads();
    }

#pragma unroll
    for (int i = 0; i < 8; i++) {
        float rlo, rhi;
        unpack2(rs2[i], rlo, rhi);
        float inv = 1.0f / (1e-9f + rlo);
        int row = n0 + ty * 8 + i;
        int base = (b * NPTS + row) * CIN + tx * 8;
#pragma unroll
        for (int jj = 0; jj < 4; jj++) {
            float a0, a1;
            unpack2(acc[i][jj], a0, a1);
            float2 o;
            o.x = a0 * inv;
            o.y = a1 * inv;
            *(float2*)&g_xr[base + jj * 2] = o;
        }
    }
}

// ---------------- K5: y = leaky(BN((x - x_r) @ Wp^T)) + x ----------------
__global__ __launch_bounds__(256) void k_proj(const float* __restrict__ x,
                                              const float* __restrict__ Wp,
                                              const float* __restrict__ gamma,
                                              const float* __restrict__ beta,
                                              const float* __restrict__ mean,
                                              const float* __restrict__ var,
                                              float* __restrict__ out) {
    __shared__ float As[128][33];
    __shared__ float Ws[128][33];
    const int tid = threadIdx.x;
    const int ty = tid >> 4, tx = tid & 15;
    const int r0 = blockIdx.x * 128;

    float acc[8][8] = {};
    for (int kc = 0; kc < CIN; kc += 32) {
#pragma unroll
        for (int u = 0; u < 16; u++) {
            int idx = u * 256 + tid;
            int row = idx >> 5, kk = idx & 31;
            int g = (r0 + row) * CIN + kc + kk;
            As[row][kk] = x[g] - g_xr[g];
            Ws[row][kk] = Wp[row * CIN + kc + kk];  // row == output channel o
        }
        __syncthreads();
#pragma unroll 8
        for (int kk = 0; kk < 32; kk++) {
            float a[8], bb[8];
#pragma unroll
            for (int i = 0; i < 8; i++) a[i] = As[ty * 8 + i][kk];
#pragma unroll
            for (int j = 0; j < 8; j++) bb[j] = Ws[tx * 8 + j][kk];
#pragma unroll
            for (int i = 0; i < 8; i++)
#pragma unroll
                for (int j = 0; j < 8; j++) acc[i][j] = fmaf(a[i], bb[j], acc[i][j]);
        }
        __syncthreads();
    }

#pragma unroll
    for (int i = 0; i < 8; i++) {
        int r = r0 + ty * 8 + i;
#pragma unroll
        for (int j = 0; j < 8; j++) {
            int o = tx * 8 + j;
            float sc = gamma[o] * rsqrtf(var[o] + 1e-5f);
            float yv = (acc[i][j] - mean[o]) * sc + beta[o];
            yv = (yv >= 0.f) ? yv : 0.01f * yv;
            out[r * CIN + o] = yv + x[r * CIN + o];
        }
    }
}

// ---------------- launch ----------------
extern "C" void kernel_launch(void* const* d_in, const int* in_sizes, int n_in,
                              void* d_out, int out_size) {
    const float* x     = (const float*)d_in[0];
    const float* Wq    = (const float*)d_in[1];
    const float* Wk    = (const float*)d_in[2];
    const float* Wv    = (const float*)d_in[3];
    const float* Wp    = (const float*)d_in[4];
    const float* gamma = (const float*)d_in[5];
    const float* beta  = (const float*)d_in[6];
    const float* mean  = (const float*)d_in[7];
    const float* var   = (const float*)d_in[8];
    float* out = (float*)d_out;

    k_qkv<<<dim3((BATCH * NPTS) / 64, 3), 256>>>(x, Wq, Wk, Wv);
    k_energy<<<dim3(NPTS / 128, NPTS / 128, BATCH), 256>>>();
    k_colstats_part<<<dim3(NPTS / 256, NSEG, BATCH), 256>>>();
    k_colstats_merge<<<(BATCH * NPTS) / 256, 256>>>();
    k_xr<<<dim3(NPTS / 128, BATCH), 256>>>();
    k_proj<<<(BATCH * NPTS) / 128, 256>>>(x, Wp, gamma, beta, mean, var, out);
}

// round 3
// speedup vs baseline: 2.2371x; 2.2371x over previous
#include <cuda_runtime.h>
#include <cuda_bf16.h>
#include <cstdint>

#define BATCH 8
#define NPTS 2048
#define CIN 128
#define DQK 32
#define NSEG 8
#define VROWS 144   // 128 v channels + ones row (128) + 15 zero pad rows

// ---------------- scratch (device globals) ----------------
__device__ __nv_bfloat16 g_qh[BATCH * NPTS * DQK];
__device__ __nv_bfloat16 g_kh[BATCH * NPTS * DQK];
__device__ __nv_bfloat16 g_vTh[(size_t)BATCH * VROWS * NPTS];  // [b][c][m]
__device__ float g_E[(size_t)BATCH * NPTS * NPTS];             // 134 MB
__device__ float g_xr[BATCH * NPTS * CIN];
__device__ float g_pmax[BATCH * NPTS * NSEG];
__device__ float g_psum[BATCH * NPTS * NSEG];
__device__ float g_cmax[BATCH * NPTS];
__device__ float g_cinv[BATCH * NPTS];

// ---------------- warp MMA helpers (sm_80+ PTX; no arch-feature gate) ----------------
__device__ __forceinline__ uint32_t smem_u32(const void* p) {
    uint32_t a;
    asm("{ .reg .u64 t; cvta.to.shared.u64 t, %1; cvt.u32.u64 %0, t; }" : "=r"(a) : "l"(p));
    return a;
}
__device__ __forceinline__ void ldsm_x4(uint32_t* r, uint32_t addr) {
    asm volatile("ldmatrix.sync.aligned.m8n8.x4.shared.b16 {%0,%1,%2,%3}, [%4];"
                 : "=r"(r[0]), "=r"(r[1]), "=r"(r[2]), "=r"(r[3]) : "r"(addr));
}
__device__ __forceinline__ void ldsm_x2(uint32_t& r0, uint32_t& r1, uint32_t addr) {
    asm volatile("ldmatrix.sync.aligned.m8n8.x2.shared.b16 {%0,%1}, [%2];"
                 : "=r"(r0), "=r"(r1) : "r"(addr));
}
__device__ __forceinline__ void mma16816(float* c, const uint32_t* a, uint32_t b0, uint32_t b1) {
    asm volatile(
        "mma.sync.aligned.m16n8k16.row.col.f32.bf16.bf16.f32 "
        "{%0,%1,%2,%3}, {%4,%5,%6,%7}, {%8,%9}, {%0,%1,%2,%3};"
        : "+f"(c[0]), "+f"(c[1]), "+f"(c[2]), "+f"(c[3])
        : "r"(a[0]), "r"(a[1]), "r"(a[2]), "r"(a[3]), "r"(b0), "r"(b1));
}

// ---------------- K1: q,k,v = x @ {Wq,Wk,Wv}^T -> bf16 (v transposed) ----------------
__global__ __launch_bounds__(256) void k_qkv(const float* __restrict__ x,
                                             const float* __restrict__ Wq,
                                             const float* __restrict__ Wk,
                                             const float* __restrict__ Wv) {
    __shared__ float As[64][33];
    __shared__ float Ws[64][33];
    const int tid = threadIdx.x;
    const int ty = tid >> 4, tx = tid & 15;
    const int r0 = blockIdx.x * 64;
    const int c0 = blockIdx.y * 64;   // [0,192): 0-31 q, 32-63 k, 64-191 v

    float acc[4][4] = {};
    for (int kc = 0; kc < CIN; kc += 32) {
#pragma unroll
        for (int u = 0; u < 8; u++) {
            int idx = u * 256 + tid;
            int row = idx >> 5, kk = idx & 31;
            As[row][kk] = x[(r0 + row) * CIN + kc + kk];
        }
#pragma unroll
        for (int u = 0; u < 8; u++) {
            int idx = u * 256 + tid;
            int col = idx >> 5, kk = idx & 31;
            int c = c0 + col;
            const float* wp;
            int wr;
            if (c < 32)      { wp = Wq; wr = c; }
            else if (c < 64) { wp = Wk; wr = c - 32; }
            else             { wp = Wv; wr = c - 64; }
            Ws[col][kk] = wp[wr * CIN + kc + kk];
        }
        __syncthreads();
#pragma unroll 8
        for (int kk = 0; kk < 32; kk++) {
            float a[4], bb[4];
#pragma unroll
            for (int i = 0; i < 4; i++) a[i] = As[ty * 4 + i][kk];
#pragma unroll
            for (int j = 0; j < 4; j++) bb[j] = Ws[tx * 4 + j][kk];
#pragma unroll
            for (int i = 0; i < 4; i++)
#pragma unroll
                for (int j = 0; j < 4; j++) acc[i][j] = fmaf(a[i], bb[j], acc[i][j]);
        }
        __syncthreads();
    }
#pragma unroll
    for (int i = 0; i < 4; i++) {
        int r = r0 + ty * 4 + i;
        int bb = r >> 11, n = r & (NPTS - 1);
#pragma unroll
        for (int j = 0; j < 4; j++) {
            int c = c0 + tx * 4 + j;
            __nv_bfloat16 v = __float2bfloat16(acc[i][j]);
            if (c < 32)      g_qh[(bb * NPTS + n) * DQK + c] = v;
            else if (c < 64) g_kh[(bb * NPTS + n) * DQK + (c - 32)] = v;
            else             g_vTh[((size_t)bb * VROWS + (c - 64)) * NPTS + n] = v;
        }
    }
}

// ---------------- K1b: ones row (c=128) + zero pad rows 129..143 ----------------
__global__ __launch_bounds__(256) void k_init_ones() {
    int idx = blockIdx.x * 256 + threadIdx.x;   // over BATCH * 16 * NPTS
    int b = idx / (16 * NPTS);
    int r = idx - b * 16 * NPTS;
    int c = 128 + r / NPTS;
    int m = r & (NPTS - 1);
    g_vTh[((size_t)b * VROWS + c) * NPTS + m] = __float2bfloat16(c == 128 ? 1.0f : 0.0f);
}

// ---------------- K2: E = q @ k^T via mma.sync (128x128 tile, K=32) ----------------
#define QKS 40   // padded stride (bf16 elems) -> 80B, ldmatrix conflict-free
__global__ __launch_bounds__(256) void k_energy_mma() {
    __shared__ __nv_bfloat16 Qs[128 * QKS];
    __shared__ __nv_bfloat16 Ks[128 * QKS];
    const int tid = threadIdx.x, w = tid >> 5, l = tid & 31;
    const int b = blockIdx.z, n0 = blockIdx.x * 128, m0 = blockIdx.y * 128;

    const uint4* qsrc = (const uint4*)&g_qh[(b * NPTS + n0) * DQK];
    const uint4* ksrc = (const uint4*)&g_kh[(b * NPTS + m0) * DQK];
#pragma unroll
    for (int i = tid; i < 512; i += 256) {       // 128 rows x 4 uint4
        int row = i >> 2, j = i & 3;
        *(uint4*)&Qs[row * QKS + j * 8] = qsrc[i];
        *(uint4*)&Ks[row * QKS + j * 8] = ksrc[i];
    }
    __syncthreads();

    const int wn = w & 3, wm = w >> 2;           // warp tile: 32n x 64m
    const uint32_t qb = smem_u32(Qs), kb = smem_u32(Ks);
    float acc[2][8][4] = {};

#pragma unroll
    for (int ks = 0; ks < 2; ks++) {
        uint32_t a[2][4];
#pragma unroll
        for (int i = 0; i < 2; i++)
            ldsm_x4(a[i], qb + ((wn * 32 + i * 16 + (l & 15)) * QKS + ks * 16) * 2 + (l >> 4) * 16);
#pragma unroll
        for (int j = 0; j < 8; j++) {
            uint32_t b0, b1;
            ldsm_x2(b0, b1, kb + ((wm * 64 + j * 8 + (l & 7)) * QKS + ks * 16) * 2 + ((l >> 3) & 1) * 16);
#pragma unroll
            for (int i = 0; i < 2; i++) mma16816(acc[i][j], a[i], b0, b1);
        }
    }

    const int g = l >> 2, tig = l & 3;
#pragma unroll
    for (int i = 0; i < 2; i++) {
        int row = n0 + wn * 32 + i * 16 + g;
#pragma unroll
        for (int j = 0; j < 8; j++) {
            int col = m0 + wm * 64 + j * 8 + tig * 2;
            float2 lo = make_float2(acc[i][j][0], acc[i][j][1]);
            float2 hi = make_float2(acc[i][j][2], acc[i][j][3]);
            *(float2*)&g_E[((size_t)b * NPTS + row) * NPTS + col] = lo;
            *(float2*)&g_E[((size_t)b * NPTS + row + 8) * NPTS + col] = hi;
        }
    }
}

// ---------------- K3a: per-column (query axis) online softmax partials ----------------
__global__ __launch_bounds__(256) void k_colstats_part() {
    const int b = blockIdx.z;
    const int m = blockIdx.x * 256 + threadIdx.x;
    const int seg = blockIdx.y;
    const float* col = &g_E[(size_t)b * NPTS * NPTS + m];
    const int n0 = seg * (NPTS / NSEG);
    float mx = -1e30f, s = 0.f;
    for (int n = n0; n < n0 + NPTS / NSEG; n += 8) {
        float v[8];
#pragma unroll
        for (int u = 0; u < 8; u++) v[u] = col[(size_t)(n + u) * NPTS];
#pragma unroll
        for (int u = 0; u < 8; u++) {
            float vv = v[u];
            if (vv > mx) { s = s * __expf(mx - vv) + 1.f; mx = vv; }
            else         { s += __expf(vv - mx); }
        }
    }
    g_pmax[(b * NPTS + m) * NSEG + seg] = mx;
    g_psum[(b * NPTS + m) * NSEG + seg] = s;
}

// ---------------- K3b: merge partials -> cmax, 1/csum ----------------
__global__ __launch_bounds__(256) void k_colstats_merge() {
    const int idx = blockIdx.x * 256 + threadIdx.x;
    float pm[NSEG], ps[NSEG];
    float mx = -1e30f;
#pragma unroll
    for (int g = 0; g < NSEG; g++) {
        pm[g] = g_pmax[idx * NSEG + g];
        ps[g] = g_psum[idx * NSEG + g];
        mx = fmaxf(mx, pm[g]);
    }
    float s = 0.f;
#pragma unroll
    for (int g = 0; g < NSEG; g++) s += ps[g] * __expf(pm[g] - mx);
    g_cmax[idx] = mx;
    g_cinv[idx] = 1.0f / s;
}

// ---------------- K4: x_r = rownorm(P) @ v via mma.sync ----------------
// Block: 64 query rows; loop 64-key chunks. vT ones row at c=128 -> col128 = rowsum(P).
#define PSS 72   // padded stride (bf16) -> 144B
__global__ __launch_bounds__(256) void k_xr_mma() {
    __shared__ __nv_bfloat16 Ps[64 * PSS];
    __shared__ __nv_bfloat16 Vts[VROWS * PSS];
    __shared__ float rsum[64];
    __shared__ float cmv[64], civ[64];
    const int tid = threadIdx.x, w = tid >> 5, l = tid & 31;
    const int b = blockIdx.y, n0 = blockIdx.x * 64;
    const int wn = w & 3, wc = w >> 2;           // warp tile: 16n x 72c

    const float* Ebase = &g_E[((size_t)b * NPTS + n0) * NPTS];
    const uint32_t pb = smem_u32(Ps), vb = smem_u32(Vts);
    float acc[9][4] = {};

    for (int mc = 0; mc < NPTS; mc += 64) {
        __syncthreads();
        if (tid < 64) {
            cmv[tid] = g_cmax[b * NPTS + mc + tid];
            civ[tid] = g_cinv[b * NPTS + mc + tid];
        }
        __syncthreads();
        // P tile 64n x 64m
#pragma unroll
        for (int i = tid; i < 1024; i += 256) {
            int row = i >> 4, jj = (i & 15) * 4;
            float4 e = *(const float4*)&Ebase[(size_t)row * NPTS + mc + jj];
            float p0 = __expf(e.x - cmv[jj + 0]) * civ[jj + 0];
            float p1 = __expf(e.y - cmv[jj + 1]) * civ[jj + 1];
            float p2 = __expf(e.z - cmv[jj + 2]) * civ[jj + 2];
            float p3 = __expf(e.w - cmv[jj + 3]) * civ[jj + 3];
            __nv_bfloat162* d = (__nv_bfloat162*)&Ps[row * PSS + jj];
            d[0] = __nv_bfloat162(__float2bfloat16(p0), __float2bfloat16(p1));
            d[1] = __nv_bfloat162(__float2bfloat16(p2), __float2bfloat16(p3));
        }
        // V tile 144c x 64m from transposed vT
#pragma unroll
        for (int i = tid; i < 1152; i += 256) {
            int row = i >> 3, j = i & 7;
            uint4 v = *(const uint4*)&g_vTh[((size_t)b * VROWS + row) * NPTS + mc + j * 8];
            *(uint4*)&Vts[row * PSS + j * 8] = v;
        }
        __syncthreads();

#pragma unroll
        for (int ks = 0; ks < 4; ks++) {
            uint32_t a[4];
            ldsm_x4(a, pb + ((wn * 16 + (l & 15)) * PSS + ks * 16) * 2 + (l >> 4) * 16);
#pragma unroll
            for (int j = 0; j < 9; j++) {
                uint32_t b0, b1;
                ldsm_x2(b0, b1, vb + ((wc * 72 + j * 8 + (l & 7)) * PSS + ks * 16) * 2 + ((l >> 3) & 1) * 16);
                mma16816(acc[j], a, b0, b1);
            }
        }
    }
    __syncthreads();

    const int g = l >> 2, tig = l & 3;
    if (wc == 1 && tig == 0) {           // frag j=7 col 128 = rowsum
        rsum[wn * 16 + g] = acc[7][0];
        rsum[wn * 16 + g + 8] = acc[7][2];
    }
    __syncthreads();

    const int row = wn * 16 + g;
    const float inv0 = 1.0f / (1e-9f + rsum[row]);
    const float inv1 = 1.0f / (1e-9f + rsum[row + 8]);
    float* dst0 = &g_xr[((size_t)b * NPTS + n0 + row) * CIN];
    float* dst1 = &g_xr[((size_t)b * NPTS + n0 + row + 8) * CIN];
#pragma unroll
    for (int j = 0; j < 9; j++) {
        int col = wc * 72 + j * 8 + tig * 2;
        if (col < 128) {
            *(float2*)&dst0[col] = make_float2(acc[j][0] * inv0, acc[j][1] * inv0);
            *(float2*)&dst1[col] = make_float2(acc[j][2] * inv1, acc[j][3] * inv1);
        }
    }
}

// ---------------- K5: y = leaky(BN((x - x_r) @ Wp^T)) + x ----------------
__global__ __launch_bounds__(256) void k_proj(const float* __restrict__ x,
                                              const float* __restrict__ Wp,
                                              const float* __restrict__ gamma,
                                              const float* __restrict__ beta,
                                              const float* __restrict__ mean,
                                              const float* __restrict__ var,
                                              float* __restrict__ out) {
    __shared__ float As[128][33];
    __shared__ float Ws[128][33];
    const int tid = threadIdx.x;
    const int ty = tid >> 4, tx = tid & 15;
    const int r0 = blockIdx.x * 128;

    float acc[8][8] = {};
    for (int kc = 0; kc < CIN; kc += 32) {
#pragma unroll
        for (int u = 0; u < 16; u++) {
            int idx = u * 256 + tid;
            int row = idx >> 5, kk = idx & 31;
            int g = (r0 + row) * CIN + kc + kk;
            As[row][kk] = x[g] - g_xr[g];
            Ws[row][kk] = Wp[row * CIN + kc + kk];
        }
        __syncthreads();
#pragma unroll 8
        for (int kk = 0; kk < 32; kk++) {
            float a[8], bb[8];
#pragma unroll
            for (int i = 0; i < 8; i++) a[i] = As[ty * 8 + i][kk];
#pragma unroll
            for (int j = 0; j < 8; j++) bb[j] = Ws[tx * 8 + j][kk];
#pragma unroll
            for (int i = 0; i < 8; i++)
#pragma unroll
                for (int j = 0; j < 8; j++) acc[i][j] = fmaf(a[i], bb[j], acc[i][j]);
        }
        __syncthreads();
    }

#pragma unroll
    for (int i = 0; i < 8; i++) {
        int r = r0 + ty * 8 + i;
#pragma unroll
        for (int j = 0; j < 8; j++) {
            int o = tx * 8 + j;
            float sc = gamma[o] * rsqrtf(var[o] + 1e-5f);
            float yv = (acc[i][j] - mean[o]) * sc + beta[o];
            yv = (yv >= 0.f) ? yv : 0.01f * yv;
            out[r * CIN + o] = yv + x[r * CIN + o];
        }
    }
}

// ---------------- launch ----------------
extern "C" void kernel_launch(void* const* d_in, const int* in_sizes, int n_in,
                              void* d_out, int out_size) {
    const float* x     = (const float*)d_in[0];
    const float* Wq    = (const float*)d_in[1];
    const float* Wk    = (const float*)d_in[2];
    const float* Wv    = (const float*)d_in[3];
    const float* Wp    = (const float*)d_in[4];
    const float* gamma = (const float*)d_in[5];
    const float* beta  = (const float*)d_in[6];
    const float* mean  = (const float*)d_in[7];
    const float* var   = (const float*)d_in[8];
    float* out = (float*)d_out;

    k_qkv<<<dim3((BATCH * NPTS) / 64, 3), 256>>>(x, Wq, Wk, Wv);
    k_init_ones<<<(BATCH * 16 * NPTS) / 256, 256>>>();
    k_energy_mma<<<dim3(NPTS / 128, NPTS / 128, BATCH), 256>>>();
    k_colstats_part<<<dim3(NPTS / 256, NSEG, BATCH), 256>>>();
    k_colstats_merge<<<(BATCH * NPTS) / 256, 256>>>();
    k_xr_mma<<<dim3(NPTS / 64, BATCH), 256>>>();
    k_proj<<<(BATCH * NPTS) / 128, 256>>>(x, Wp, gamma, beta, mean, var, out);
}

// round 4
// speedup vs baseline: 2.6616x; 1.1898x over previous
#include <cuda_runtime.h>
#include <cuda_bf16.h>
#include <cuda_fp16.h>
#include <cstdint>

#define BATCH 8
#define NPTS 2048
#define CIN 128
#define DQK 32
#define NSEG 16
#define VROWS 144   // 128 v channels + ones row (128) + 15 zero pad rows

// ---------------- scratch (device globals) ----------------
__device__ __nv_bfloat16 g_qh[BATCH * NPTS * DQK];
__device__ __nv_bfloat16 g_kh[BATCH * NPTS * DQK];
__device__ __nv_bfloat16 g_vTh[(size_t)BATCH * VROWS * NPTS];  // [b][c][m]
__device__ __half g_Eh[(size_t)BATCH * NPTS * NPTS];           // 67 MB fp16 energy
__device__ float g_xr[BATCH * NPTS * CIN];
__device__ float g_pmax[BATCH * NPTS * NSEG];
__device__ float g_psum[BATCH * NPTS * NSEG];
__device__ float g_cmax[BATCH * NPTS];
__device__ float g_cinv[BATCH * NPTS];

// ---------------- warp MMA helpers ----------------
__device__ __forceinline__ uint32_t smem_u32(const void* p) {
    uint32_t a;
    asm("{ .reg .u64 t; cvta.to.shared.u64 t, %1; cvt.u32.u64 %0, t; }" : "=r"(a) : "l"(p));
    return a;
}
__device__ __forceinline__ void ldsm_x4(uint32_t* r, uint32_t addr) {
    asm volatile("ldmatrix.sync.aligned.m8n8.x4.shared.b16 {%0,%1,%2,%3}, [%4];"
                 : "=r"(r[0]), "=r"(r[1]), "=r"(r[2]), "=r"(r[3]) : "r"(addr));
}
__device__ __forceinline__ void ldsm_x2(uint32_t& r0, uint32_t& r1, uint32_t addr) {
    asm volatile("ldmatrix.sync.aligned.m8n8.x2.shared.b16 {%0,%1}, [%2];"
                 : "=r"(r0), "=r"(r1) : "r"(addr));
}
__device__ __forceinline__ void mma16816(float* c, const uint32_t* a, uint32_t b0, uint32_t b1) {
    asm volatile(
        "mma.sync.aligned.m16n8k16.row.col.f32.bf16.bf16.f32 "
        "{%0,%1,%2,%3}, {%4,%5,%6,%7}, {%8,%9}, {%0,%1,%2,%3};"
        : "+f"(c[0]), "+f"(c[1]), "+f"(c[2]), "+f"(c[3])
        : "r"(a[0]), "r"(a[1]), "r"(a[2]), "r"(a[3]), "r"(b0), "r"(b1));
}

// ---------------- K1: q,k,v = x @ {Wq,Wk,Wv}^T -> bf16 (v transposed) ----------------
__global__ __launch_bounds__(256) void k_qkv(const float* __restrict__ x,
                                             const float* __restrict__ Wq,
                                             const float* __restrict__ Wk,
                                             const float* __restrict__ Wv) {
    __shared__ float As[64][33];
    __shared__ float Ws[64][33];
    const int tid = threadIdx.x;
    const int ty = tid >> 4, tx = tid & 15;
    const int r0 = blockIdx.x * 64;
    const int c0 = blockIdx.y * 64;   // [0,192): 0-31 q, 32-63 k, 64-191 v

    float acc[4][4] = {};
    for (int kc = 0; kc < CIN; kc += 32) {
#pragma unroll
        for (int u = 0; u < 8; u++) {
            int idx = u * 256 + tid;
            int row = idx >> 5, kk = idx & 31;
            As[row][kk] = x[(r0 + row) * CIN + kc + kk];
        }
#pragma unroll
        for (int u = 0; u < 8; u++) {
            int idx = u * 256 + tid;
            int col = idx >> 5, kk = idx & 31;
            int c = c0 + col;
            const float* wp;
            int wr;
            if (c < 32)      { wp = Wq; wr = c; }
            else if (c < 64) { wp = Wk; wr = c - 32; }
            else             { wp = Wv; wr = c - 64; }
            Ws[col][kk] = wp[wr * CIN + kc + kk];
        }
        __syncthreads();
#pragma unroll 8
        for (int kk = 0; kk < 32; kk++) {
            float a[4], bb[4];
#pragma unroll
            for (int i = 0; i < 4; i++) a[i] = As[ty * 4 + i][kk];
#pragma unroll
            for (int j = 0; j < 4; j++) bb[j] = Ws[tx * 4 + j][kk];
#pragma unroll
            for (int i = 0; i < 4; i++)
#pragma unroll
                for (int j = 0; j < 4; j++) acc[i][j] = fmaf(a[i], bb[j], acc[i][j]);
        }
        __syncthreads();
    }
#pragma unroll
    for (int i = 0; i < 4; i++) {
        int r = r0 + ty * 4 + i;
        int bb = r >> 11, n = r & (NPTS - 1);
#pragma unroll
        for (int j = 0; j < 4; j++) {
            int c = c0 + tx * 4 + j;
            __nv_bfloat16 v = __float2bfloat16(acc[i][j]);
            if (c < 32)      g_qh[(bb * NPTS + n) * DQK + c] = v;
            else if (c < 64) g_kh[(bb * NPTS + n) * DQK + (c - 32)] = v;
            else             g_vTh[((size_t)bb * VROWS + (c - 64)) * NPTS + n] = v;
        }
    }
}

// ---------------- K1b: ones row (c=128) + zero pad rows 129..143 ----------------
__global__ __launch_bounds__(256) void k_init_ones() {
    int idx = blockIdx.x * 256 + threadIdx.x;   // over BATCH * 16 * NPTS
    int b = idx / (16 * NPTS);
    int r = idx - b * 16 * NPTS;
    int c = 128 + r / NPTS;
    int m = r & (NPTS - 1);
    g_vTh[((size_t)b * VROWS + c) * NPTS + m] = __float2bfloat16(c == 128 ? 1.0f : 0.0f);
}

// ---------------- K2: E = q @ k^T + fused per-tile column stats (fp16 E out) ----------------
#define QKS 40   // padded stride (bf16 elems)
__global__ __launch_bounds__(256) void k_energy_stats() {
    __shared__ __nv_bfloat16 Qs[128 * QKS];
    __shared__ __nv_bfloat16 Ks[128 * QKS];
    __shared__ float sMax[4][128];
    __shared__ float sSum[4][128];
    __shared__ float sColMax[128];
    const int tid = threadIdx.x, w = tid >> 5, l = tid & 31;
    const int b = blockIdx.z, n0 = blockIdx.x * 128, m0 = blockIdx.y * 128;

    const uint4* qsrc = (const uint4*)&g_qh[(b * NPTS + n0) * DQK];
    const uint4* ksrc = (const uint4*)&g_kh[(b * NPTS + m0) * DQK];
#pragma unroll
    for (int i = tid; i < 512; i += 256) {
        int row = i >> 2, j = i & 3;
        *(uint4*)&Qs[row * QKS + j * 8] = qsrc[i];
        *(uint4*)&Ks[row * QKS + j * 8] = ksrc[i];
    }
    __syncthreads();

    const int wn = w & 3, wm = w >> 2;          // warp tile: 32n x 64m
    const uint32_t qb = smem_u32(Qs), kb = smem_u32(Ks);
    float acc[2][8][4] = {};

#pragma unroll
    for (int ks = 0; ks < 2; ks++) {
        uint32_t a[2][4];
#pragma unroll
        for (int i = 0; i < 2; i++)
            ldsm_x4(a[i], qb + ((wn * 32 + i * 16 + (l & 15)) * QKS + ks * 16) * 2 + (l >> 4) * 16);
#pragma unroll
        for (int j = 0; j < 8; j++) {
            uint32_t b0, b1;
            ldsm_x2(b0, b1, kb + ((wm * 64 + j * 8 + (l & 7)) * QKS + ks * 16) * 2 + ((l >> 3) & 1) * 16);
#pragma unroll
            for (int i = 0; i < 2; i++) mma16816(acc[i][j], a[i], b0, b1);
        }
    }

    // Round accs to fp16 in place (stats and store stay consistent).
#pragma unroll
    for (int i = 0; i < 2; i++)
#pragma unroll
        for (int j = 0; j < 8; j++)
#pragma unroll
            for (int q = 0; q < 4; q++) acc[i][j][q] = __half2float(__float2half(acc[i][j][q]));

    // Store fp16 E.
    const int g = l >> 2, tig = l & 3;
#pragma unroll
    for (int i = 0; i < 2; i++) {
        int row = n0 + wn * 32 + i * 16 + g;
#pragma unroll
        for (int j = 0; j < 8; j++) {
            int col = m0 + wm * 64 + j * 8 + tig * 2;
            *(__half2*)&g_Eh[((size_t)b * NPTS + row) * NPTS + col] =
                __floats2half2_rn(acc[i][j][0], acc[i][j][1]);
            *(__half2*)&g_Eh[((size_t)b * NPTS + row + 8) * NPTS + col] =
                __floats2half2_rn(acc[i][j][2], acc[i][j][3]);
        }
    }

    // ---- Phase 1: column max over the 128 query rows of this tile ----
    float lm[8][2];
#pragma unroll
    for (int j = 0; j < 8; j++) {
        lm[j][0] = fmaxf(fmaxf(acc[0][j][0], acc[0][j][2]), fmaxf(acc[1][j][0], acc[1][j][2]));
        lm[j][1] = fmaxf(fmaxf(acc[0][j][1], acc[0][j][3]), fmaxf(acc[1][j][1], acc[1][j][3]));
    }
#pragma unroll
    for (int off = 4; off <= 16; off <<= 1)
#pragma unroll
        for (int j = 0; j < 8; j++) {
            lm[j][0] = fmaxf(lm[j][0], __shfl_xor_sync(0xFFFFFFFFu, lm[j][0], off));
            lm[j][1] = fmaxf(lm[j][1], __shfl_xor_sync(0xFFFFFFFFu, lm[j][1], off));
        }
    if (g == 0) {
#pragma unroll
        for (int j = 0; j < 8; j++) {
            int col = wm * 64 + j * 8 + tig * 2;
            sMax[wn][col] = lm[j][0];
            sMax[wn][col + 1] = lm[j][1];
        }
    }
    __syncthreads();
    if (tid < 128)
        sColMax[tid] = fmaxf(fmaxf(sMax[0][tid], sMax[1][tid]), fmaxf(sMax[2][tid], sMax[3][tid]));
    __syncthreads();

    // ---- Phase 2: column sum of exp(e - colmax) ----
    float lsum[8][2];
#pragma unroll
    for (int j = 0; j < 8; j++) {
        int col = wm * 64 + j * 8 + tig * 2;
        float m0c = sColMax[col], m1c = sColMax[col + 1];
        lsum[j][0] = __expf(acc[0][j][0] - m0c) + __expf(acc[0][j][2] - m0c) +
                     __expf(acc[1][j][0] - m0c) + __expf(acc[1][j][2] - m0c);
        lsum[j][1] = __expf(acc[0][j][1] - m1c) + __expf(acc[0][j][3] - m1c) +
                     __expf(acc[1][j][1] - m1c) + __expf(acc[1][j][3] - m1c);
    }
#pragma unroll
    for (int off = 4; off <= 16; off <<= 1)
#pragma unroll
        for (int j = 0; j < 8; j++) {
            lsum[j][0] += __shfl_xor_sync(0xFFFFFFFFu, lsum[j][0], off);
            lsum[j][1] += __shfl_xor_sync(0xFFFFFFFFu, lsum[j][1], off);
        }
    if (g == 0) {
#pragma unroll
        for (int j = 0; j < 8; j++) {
            int col = wm * 64 + j * 8 + tig * 2;
            sSum[wn][col] = lsum[j][0];
            sSum[wn][col + 1] = lsum[j][1];
        }
    }
    __syncthreads();
    if (tid < 128) {
        float s = sSum[0][tid] + sSum[1][tid] + sSum[2][tid] + sSum[3][tid];
        int m = m0 + tid;
        g_pmax[(b * NPTS + m) * NSEG + blockIdx.x] = sColMax[tid];
        g_psum[(b * NPTS + m) * NSEG + blockIdx.x] = s;
    }
}

// ---------------- K3: merge partials -> cmax, 1/csum ----------------
__global__ __launch_bounds__(256) void k_colstats_merge() {
    const int idx = blockIdx.x * 256 + threadIdx.x;
    float pm[NSEG], ps[NSEG];
    float mx = -1e30f;
#pragma unroll
    for (int g = 0; g < NSEG; g++) {
        pm[g] = g_pmax[idx * NSEG + g];
        ps[g] = g_psum[idx * NSEG + g];
        mx = fmaxf(mx, pm[g]);
    }
    float s = 0.f;
#pragma unroll
    for (int g = 0; g < NSEG; g++) s += ps[g] * __expf(pm[g] - mx);
    g_cmax[idx] = mx;
    g_cinv[idx] = 1.0f / s;
}

// ---------------- K4: x_r = rownorm(P) @ v via mma.sync (fp16 E in) ----------------
#define PSS 72   // padded stride (bf16)
__global__ __launch_bounds__(256) void k_xr_mma() {
    __shared__ __nv_bfloat16 Ps[64 * PSS];
    __shared__ __nv_bfloat16 Vts[VROWS * PSS];
    __shared__ float rsum[64];
    __shared__ float cmv[64], civ[64];
    const int tid = threadIdx.x, w = tid >> 5, l = tid & 31;
    const int b = blockIdx.y, n0 = blockIdx.x * 64;
    const int wn = w & 3, wc = w >> 2;           // warp tile: 16n x 72c

    const __half* Ebase = &g_Eh[((size_t)b * NPTS + n0) * NPTS];
    const uint32_t pb = smem_u32(Ps), vb = smem_u32(Vts);
    float acc[9][4] = {};

    for (int mc = 0; mc < NPTS; mc += 64) {
        __syncthreads();
        if (tid < 64) {
            cmv[tid] = g_cmax[b * NPTS + mc + tid];
            civ[tid] = g_cinv[b * NPTS + mc + tid];
        }
        __syncthreads();
        // P tile 64n x 64m from fp16 E
#pragma unroll
        for (int i = tid; i < 512; i += 256) {
            int row = i >> 3, jj = (i & 7) * 8;
            uint4 raw = *(const uint4*)&Ebase[(size_t)row * NPTS + mc + jj];
            __half2 h0 = *(__half2*)&raw.x, h1 = *(__half2*)&raw.y;
            __half2 h2 = *(__half2*)&raw.z, h3 = *(__half2*)&raw.w;
            float2 f0 = __half22float2(h0), f1 = __half22float2(h1);
            float2 f2 = __half22float2(h2), f3 = __half22float2(h3);
            float p0 = __expf(f0.x - cmv[jj + 0]) * civ[jj + 0];
            float p1 = __expf(f0.y - cmv[jj + 1]) * civ[jj + 1];
            float p2 = __expf(f1.x - cmv[jj + 2]) * civ[jj + 2];
            float p3 = __expf(f1.y - cmv[jj + 3]) * civ[jj + 3];
            float p4 = __expf(f2.x - cmv[jj + 4]) * civ[jj + 4];
            float p5 = __expf(f2.y - cmv[jj + 5]) * civ[jj + 5];
            float p6 = __expf(f3.x - cmv[jj + 6]) * civ[jj + 6];
            float p7 = __expf(f3.y - cmv[jj + 7]) * civ[jj + 7];
            __nv_bfloat162* d = (__nv_bfloat162*)&Ps[row * PSS + jj];
            d[0] = __nv_bfloat162(__float2bfloat16(p0), __float2bfloat16(p1));
            d[1] = __nv_bfloat162(__float2bfloat16(p2), __float2bfloat16(p3));
            d[2] = __nv_bfloat162(__float2bfloat16(p4), __float2bfloat16(p5));
            d[3] = __nv_bfloat162(__float2bfloat16(p6), __float2bfloat16(p7));
        }
        // V tile 144c x 64m from transposed vT
#pragma unroll
        for (int i = tid; i < 1152; i += 256) {
            int row = i >> 3, j = i & 7;
            uint4 v = *(const uint4*)&g_vTh[((size_t)b * VROWS + row) * NPTS + mc + j * 8];
            *(uint4*)&Vts[row * PSS + j * 8] = v;
        }
        __syncthreads();

#pragma unroll
        for (int ks = 0; ks < 4; ks++) {
            uint32_t a[4];
            ldsm_x4(a, pb + ((wn * 16 + (l & 15)) * PSS + ks * 16) * 2 + (l >> 4) * 16);
#pragma unroll
            for (int j = 0; j < 9; j++) {
                uint32_t b0, b1;
                ldsm_x2(b0, b1, vb + ((wc * 72 + j * 8 + (l & 7)) * PSS + ks * 16) * 2 + ((l >> 3) & 1) * 16);
                mma16816(acc[j], a, b0, b1);
            }
        }
    }
    __syncthreads();

    const int g = l >> 2, tig = l & 3;
    if (wc == 1 && tig == 0) {           // frag j=7 col 128 = rowsum
        rsum[wn * 16 + g] = acc[7][0];
        rsum[wn * 16 + g + 8] = acc[7][2];
    }
    __syncthreads();

    const int row = wn * 16 + g;
    const float inv0 = 1.0f / (1e-9f + rsum[row]);
    const float inv1 = 1.0f / (1e-9f + rsum[row + 8]);
    float* dst0 = &g_xr[((size_t)b * NPTS + n0 + row) * CIN];
    float* dst1 = &g_xr[((size_t)b * NPTS + n0 + row + 8) * CIN];
#pragma unroll
    for (int j = 0; j < 9; j++) {
        int col = wc * 72 + j * 8 + tig * 2;
        if (col < 128) {
            *(float2*)&dst0[col] = make_float2(acc[j][0] * inv0, acc[j][1] * inv0);
            *(float2*)&dst1[col] = make_float2(acc[j][2] * inv1, acc[j][3] * inv1);
        }
    }
}

// ---------------- K5: y = leaky(BN((x - x_r) @ Wp^T)) + x ----------------
__global__ __launch_bounds__(256) void k_proj(const float* __restrict__ x,
                                              const float* __restrict__ Wp,
                                              const float* __restrict__ gamma,
                                              const float* __restrict__ beta,
                                              const float* __restrict__ mean,
                                              const float* __restrict__ var,
                                              float* __restrict__ out) {
    __shared__ float As[128][33];
    __shared__ float Ws[128][33];
    const int tid = threadIdx.x;
    const int ty = tid >> 4, tx = tid & 15;
    const int r0 = blockIdx.x * 128;

    float acc[8][8] = {};
    for (int kc = 0; kc < CIN; kc += 32) {
#pragma unroll
        for (int u = 0; u < 16; u++) {
            int idx = u * 256 + tid;
            int row = idx >> 5, kk = idx & 31;
            int g = (r0 + row) * CIN + kc + kk;
            As[row][kk] = x[g] - g_xr[g];
            Ws[row][kk] = Wp[row * CIN + kc + kk];
        }
        __syncthreads();
#pragma unroll 8
        for (int kk = 0; kk < 32; kk++) {
            float a[8], bb[8];
#pragma unroll
            for (int i = 0; i < 8; i++) a[i] = As[ty * 8 + i][kk];
#pragma unroll
            for (int j = 0; j < 8; j++) bb[j] = Ws[tx * 8 + j][kk];
#pragma unroll
            for (int i = 0; i < 8; i++)
#pragma unroll
                for (int j = 0; j < 8; j++) acc[i][j] = fmaf(a[i], bb[j], acc[i][j]);
        }
        __syncthreads();
    }

#pragma unroll
    for (int i = 0; i < 8; i++) {
        int r = r0 + ty * 8 + i;
#pragma unroll
        for (int j = 0; j < 8; j++) {
            int o = tx * 8 + j;
            float sc = gamma[o] * rsqrtf(var[o] + 1e-5f);
            float yv = (acc[i][j] - mean[o]) * sc + beta[o];
            yv = (yv >= 0.f) ? yv : 0.01f * yv;
            out[r * CIN + o] = yv + x[r * CIN + o];
        }
    }
}

// ---------------- launch ----------------
extern "C" void kernel_launch(void* const* d_in, const int* in_sizes, int n_in,
                              void* d_out, int out_size) {
    const float* x     = (const float*)d_in[0];
    const float* Wq    = (const float*)d_in[1];
    const float* Wk    = (const float*)d_in[2];
    const float* Wv    = (const float*)d_in[3];
    const float* Wp    = (const float*)d_in[4];
    const float* gamma = (const float*)d_in[5];
    const float* beta  = (const float*)d_in[6];
    const float* mean  = (const float*)d_in[7];
    const float* var   = (const float*)d_in[8];
    float* out = (float*)d_out;

    k_qkv<<<dim3((BATCH * NPTS) / 64, 3), 256>>>(x, Wq, Wk, Wv);
    k_init_ones<<<(BATCH * 16 * NPTS) / 256, 256>>>();
    k_energy_stats<<<dim3(NPTS / 128, NPTS / 128, BATCH), 256>>>();
    k_colstats_merge<<<(BATCH * NPTS) / 256, 256>>>();
    k_xr_mma<<<dim3(NPTS / 64, BATCH), 256>>>();
    k_proj<<<(BATCH * NPTS) / 128, 256>>>(x, Wp, gamma, beta, mean, var, out);
}

// round 5
// speedup vs baseline: 3.9859x; 1.4975x over previous
#include <cuda_runtime.h>
#include <cuda_bf16.h>
#include <cstdint>

#define BATCH 8
#define NPTS 2048
#define CIN 128
#define DQK 32
#define VROWS 144   // 128 v channels + ones row (128) + 15 zero pad rows

// ---------------- scratch (device globals) ----------------
__device__ __nv_bfloat16 g_qh[BATCH * NPTS * DQK];
__device__ __nv_bfloat16 g_kh[BATCH * NPTS * DQK];
__device__ __nv_bfloat16 g_vTh[(size_t)BATCH * VROWS * NPTS];  // [b][c][m]
__device__ __nv_bfloat16 g_wall[192 * CIN];                    // Wq(0-31),Wk(32-63),Wv(64-191)
__device__ __nv_bfloat16 g_wph[CIN * CIN];
__device__ float g_xr[BATCH * NPTS * CIN];
__device__ float g_cmax[BATCH * NPTS];
__device__ float g_cinv[BATCH * NPTS];

// ---------------- helpers ----------------
__device__ __forceinline__ uint32_t smem_u32(const void* p) {
    uint32_t a;
    asm("{ .reg .u64 t; cvta.to.shared.u64 t, %1; cvt.u32.u64 %0, t; }" : "=r"(a) : "l"(p));
    return a;
}
__device__ __forceinline__ void ldsm_x4(uint32_t* r, uint32_t addr) {
    asm volatile("ldmatrix.sync.aligned.m8n8.x4.shared.b16 {%0,%1,%2,%3}, [%4];"
                 : "=r"(r[0]), "=r"(r[1]), "=r"(r[2]), "=r"(r[3]) : "r"(addr));
}
__device__ __forceinline__ void mma16816(float* c, const uint32_t* a, uint32_t b0, uint32_t b1) {
    asm volatile(
        "mma.sync.aligned.m16n8k16.row.col.f32.bf16.bf16.f32 "
        "{%0,%1,%2,%3}, {%4,%5,%6,%7}, {%8,%9}, {%0,%1,%2,%3};"
        : "+f"(c[0]), "+f"(c[1]), "+f"(c[2]), "+f"(c[3])
        : "r"(a[0]), "r"(a[1]), "r"(a[2]), "r"(a[3]), "r"(b0), "r"(b1));
}
__device__ __forceinline__ uint32_t bf2u(float a, float b) {
    __nv_bfloat162 h = __nv_bfloat162(__float2bfloat16(a), __float2bfloat16(b));
    return *(uint32_t*)&h;
}

// ---------------- K0: weights -> bf16 ----------------
__global__ __launch_bounds__(256) void k_wconv(const float* __restrict__ Wq,
                                               const float* __restrict__ Wk,
                                               const float* __restrict__ Wv,
                                               const float* __restrict__ Wp) {
    int idx = blockIdx.x * 256 + threadIdx.x;
    if (idx < 192 * CIN) {
        int row = idx >> 7;
        int col = idx & 127;
        float v;
        if (row < 32)      v = Wq[row * CIN + col];
        else if (row < 64) v = Wk[(row - 32) * CIN + col];
        else               v = Wv[(row - 64) * CIN + col];
        g_wall[idx] = __float2bfloat16(v);
    } else {
        int i2 = idx - 192 * CIN;
        g_wph[i2] = __float2bfloat16(Wp[i2]);
    }
}

// ---------------- K1: q,k,v via mma.sync (bf16 x, bf16 W) ----------------
// Block: 64 rows x 64 out-cols (grid.y in {0,1,2} -> cols [0,192))
#define XS 136   // padded stride (bf16 elems) for K=128 tiles
__global__ __launch_bounds__(256) void k_qkv_mma(const float* __restrict__ x) {
    __shared__ __nv_bfloat16 Xs[64 * XS];
    __shared__ __nv_bfloat16 Ws[64 * XS];
    const int tid = threadIdx.x, w = tid >> 5, l = tid & 31;
    const int r0 = blockIdx.x * 64;
    const int c0 = blockIdx.y * 64;
    const int wn = w & 3, wc = w >> 2;   // warp: 16 rows x 32 cols

#pragma unroll
    for (int i = tid; i < 4096; i += 256) {
        int row = i >> 6, cp = i & 63;
        float2 v = *(const float2*)&x[(size_t)(r0 + row) * CIN + cp * 2];
        *(uint32_t*)&Xs[row * XS + cp * 2] = bf2u(v.x, v.y);
        *(uint32_t*)&Ws[row * XS + cp * 2] = *(const uint32_t*)&g_wall[(c0 + row) * CIN + cp * 2];
    }
    __syncthreads();

    const uint32_t xb = smem_u32(Xs), wb = smem_u32(Ws);
    float acc[4][4] = {};
#pragma unroll
    for (int kp = 0; kp < 4; kp++) {
        uint32_t a[2][4];
        ldsm_x4(a[0], xb + (16 * wn + (l & 15)) * (XS * 2) + (2 * kp) * 32 + (l >> 4) * 16);
        ldsm_x4(a[1], xb + (16 * wn + (l & 15)) * (XS * 2) + (2 * kp + 1) * 32 + (l >> 4) * 16);
#pragma unroll
        for (int j = 0; j < 4; j++) {
            uint32_t bb[4];
            ldsm_x4(bb, wb + (32 * wc + 8 * j + (l & 7)) * (XS * 2) + kp * 64 +
                            ((l >> 3) & 1) * 16 + (l >> 4) * 32);
            mma16816(acc[j], a[0], bb[0], bb[1]);
            mma16816(acc[j], a[1], bb[2], bb[3]);
        }
    }

    const int g = l >> 2, tig = l & 3;
#pragma unroll
    for (int j = 0; j < 4; j++) {
        int col = c0 + 32 * wc + 8 * j + 2 * tig;
#pragma unroll
        for (int h = 0; h < 2; h++) {
            int r = r0 + 16 * wn + g + h * 8;
            int b = r >> 11, n = r & (NPTS - 1);
            float v0 = acc[j][h * 2], v1 = acc[j][h * 2 + 1];
            if (col < 32) {
                *(uint32_t*)&g_qh[(size_t)(b * NPTS + n) * DQK + col] = bf2u(v0, v1);
            } else if (col < 64) {
                *(uint32_t*)&g_kh[(size_t)(b * NPTS + n) * DQK + col - 32] = bf2u(v0, v1);
            } else {
                int c = col - 64;
                g_vTh[((size_t)b * VROWS + c) * NPTS + n] = __float2bfloat16(v0);
                g_vTh[((size_t)b * VROWS + c + 1) * NPTS + n] = __float2bfloat16(v1);
            }
        }
    }
}

// ---------------- K1b: ones row (c=128) + zero pad rows 129..143 ----------------
__global__ __launch_bounds__(256) void k_init_ones() {
    int idx = blockIdx.x * 256 + threadIdx.x;   // over BATCH * 16 * NPTS
    int b = idx / (16 * NPTS);
    int r = idx - b * 16 * NPTS;
    int c = 128 + r / NPTS;
    int m = r & (NPTS - 1);
    g_vTh[((size_t)b * VROWS + c) * NPTS + m] = __float2bfloat16(c == 128 ? 1.0f : 0.0f);
}

// ---------------- K2: column softmax stats (E never stored) ----------------
// Block: 128 key-cols (m) x batch; loops 16 query tiles of 128 rows.
#define QKS 40
__global__ __launch_bounds__(256) void k_stats() {
    __shared__ __nv_bfloat16 Qs[128 * QKS];
    __shared__ __nv_bfloat16 Ks[128 * QKS];
    __shared__ float sRed[8][128];
    __shared__ float tMax[16][128];
    __shared__ float tSum[16][128];
    const int tid = threadIdx.x, w = tid >> 5, l = tid & 31;
    const int b = blockIdx.y, m0 = blockIdx.x * 128;
    const int g = l >> 2, tig = l & 3;

#pragma unroll
    for (int i = tid; i < 512; i += 256) {
        int row = i >> 2, jj = i & 3;
        *(uint4*)&Ks[row * QKS + jj * 8] =
            *(const uint4*)&g_kh[(size_t)(b * NPTS + m0 + row) * DQK + jj * 8];
    }

    const uint32_t qb = smem_u32(Qs), kb = smem_u32(Ks);

    for (int t = 0; t < 16; t++) {
        __syncthreads();
#pragma unroll
        for (int i = tid; i < 512; i += 256) {
            int row = i >> 2, jj = i & 3;
            *(uint4*)&Qs[row * QKS + jj * 8] =
                *(const uint4*)&g_qh[(size_t)(b * NPTS + t * 128 + row) * DQK + jj * 8];
        }
        __syncthreads();

        float acc[16][4];
#pragma unroll
        for (int j = 0; j < 16; j++)
#pragma unroll
            for (int q = 0; q < 4; q++) acc[j][q] = 0.f;

        uint32_t a[2][4];
        ldsm_x4(a[0], qb + (16 * w + (l & 15)) * (QKS * 2) + (l >> 4) * 16);
        ldsm_x4(a[1], qb + (16 * w + (l & 15)) * (QKS * 2) + 32 + (l >> 4) * 16);
#pragma unroll
        for (int j = 0; j < 16; j++) {
            uint32_t bb[4];
            ldsm_x4(bb, kb + (8 * j + (l & 7)) * (QKS * 2) + ((l >> 3) & 1) * 16 + (l >> 4) * 32);
            mma16816(acc[j], a[0], bb[0], bb[1]);
            mma16816(acc[j], a[1], bb[2], bb[3]);
        }

        // phase 1: column max over 128 rows of this tile
#pragma unroll
        for (int j = 0; j < 16; j++) {
            float m0v = fmaxf(acc[j][0], acc[j][2]);
            float m1v = fmaxf(acc[j][1], acc[j][3]);
#pragma unroll
            for (int off = 4; off <= 16; off <<= 1) {
                m0v = fmaxf(m0v, __shfl_xor_sync(0xFFFFFFFFu, m0v, off));
                m1v = fmaxf(m1v, __shfl_xor_sync(0xFFFFFFFFu, m1v, off));
            }
            if (l < 4) {
                sRed[w][8 * j + 2 * tig] = m0v;
                sRed[w][8 * j + 2 * tig + 1] = m1v;
            }
        }
        __syncthreads();
        if (tid < 128) {
            float m = sRed[0][tid];
#pragma unroll
            for (int ww = 1; ww < 8; ww++) m = fmaxf(m, sRed[ww][tid]);
            tMax[t][tid] = m;
        }
        __syncthreads();

        // phase 2: column sumexp vs tile max
#pragma unroll
        for (int j = 0; j < 16; j++) {
            int col = 8 * j + 2 * tig;
            float tm0 = tMax[t][col], tm1 = tMax[t][col + 1];
            float s0 = __expf(acc[j][0] - tm0) + __expf(acc[j][2] - tm0);
            float s1 = __expf(acc[j][1] - tm1) + __expf(acc[j][3] - tm1);
#pragma unroll
            for (int off = 4; off <= 16; off <<= 1) {
                s0 += __shfl_xor_sync(0xFFFFFFFFu, s0, off);
                s1 += __shfl_xor_sync(0xFFFFFFFFu, s1, off);
            }
            if (l < 4) {
                sRed[w][col] = s0;
                sRed[w][col + 1] = s1;
            }
        }
        __syncthreads();
        if (tid < 128) {
            float s = 0.f;
#pragma unroll
            for (int ww = 0; ww < 8; ww++) s += sRed[ww][tid];
            tSum[t][tid] = s;
        }
    }
    __syncthreads();

    if (tid < 128) {
        float mx = -1e30f;
#pragma unroll
        for (int t = 0; t < 16; t++) mx = fmaxf(mx, tMax[t][tid]);
        float s = 0.f;
#pragma unroll
        for (int t = 0; t < 16; t++) s += tSum[t][tid] * __expf(tMax[t][tid] - mx);
        g_cmax[b * NPTS + m0 + tid] = mx;
        g_cinv[b * NPTS + m0 + tid] = 1.0f / s;
    }
}

// ---------------- K3: x_r — recompute E, exp in-register, P@v ----------------
// Block: 128 query rows x batch; loops 32 key chunks of 64. 8 warps, warp w = rows 16w.
#define VSS 72
__global__ __launch_bounds__(256) void k_xr_mma() {
    __shared__ __nv_bfloat16 Qs[128 * QKS];
    __shared__ __nv_bfloat16 Kc[64 * QKS];
    __shared__ __nv_bfloat16 Vts[VROWS * VSS];
    __shared__ float cmv[64], civ[64], rsum[128];
    const int tid = threadIdx.x, w = tid >> 5, l = tid & 31;
    const int b = blockIdx.y, n0 = blockIdx.x * 128;
    const int g = l >> 2, tig = l & 3;

#pragma unroll
    for (int i = tid; i < 512; i += 256) {
        int row = i >> 2, jj = i & 3;
        *(uint4*)&Qs[row * QKS + jj * 8] =
            *(const uint4*)&g_qh[(size_t)(b * NPTS + n0 + row) * DQK + jj * 8];
    }

    const uint32_t qb = smem_u32(Qs), kb = smem_u32(Kc), vb = smem_u32(Vts);
    float acc2[18][4];
#pragma unroll
    for (int j = 0; j < 18; j++)
#pragma unroll
        for (int q = 0; q < 4; q++) acc2[j][q] = 0.f;

    for (int mc = 0; mc < NPTS; mc += 64) {
        __syncthreads();
        if (tid < 64) {
            cmv[tid] = g_cmax[b * NPTS + mc + tid];
            civ[tid] = g_cinv[b * NPTS + mc + tid];
        }
        {
            int i = tid;                     // 256 uint4 exactly
            int row = i >> 2, jj = i & 3;
            *(uint4*)&Kc[row * QKS + jj * 8] =
                *(const uint4*)&g_kh[(size_t)(b * NPTS + mc + row) * DQK + jj * 8];
        }
#pragma unroll
        for (int i = tid; i < 1152; i += 256) {
            int row = i >> 3, jj = i & 7;
            *(uint4*)&Vts[row * VSS + jj * 8] =
                *(const uint4*)&g_vTh[((size_t)b * VROWS + row) * NPTS + mc + jj * 8];
        }
        __syncthreads();

        // E-MMA: 16 rows x 64 cols per warp (identical chain to k_stats -> bitwise equal e)
        float ae[8][4];
#pragma unroll
        for (int j = 0; j < 8; j++)
#pragma unroll
            for (int q = 0; q < 4; q++) ae[j][q] = 0.f;
        uint32_t a[2][4];
        ldsm_x4(a[0], qb + (16 * w + (l & 15)) * (QKS * 2) + (l >> 4) * 16);
        ldsm_x4(a[1], qb + (16 * w + (l & 15)) * (QKS * 2) + 32 + (l >> 4) * 16);
#pragma unroll
        for (int j = 0; j < 8; j++) {
            uint32_t bb[4];
            ldsm_x4(bb, kb + (8 * j + (l & 7)) * (QKS * 2) + ((l >> 3) & 1) * 16 + (l >> 4) * 32);
            mma16816(ae[j], a[0], bb[0], bb[1]);
            mma16816(ae[j], a[1], bb[2], bb[3]);
        }

        // exp + direct C-frag -> A-frag repack
        uint32_t a2[4][4];
#pragma unroll
        for (int s = 0; s < 4; s++) {
            int j0 = 2 * s, j1 = 2 * s + 1;
            int c00 = 8 * j0 + 2 * tig, c10 = 8 * j1 + 2 * tig;
            float p00 = __expf(ae[j0][0] - cmv[c00]) * civ[c00];
            float p01 = __expf(ae[j0][1] - cmv[c00 + 1]) * civ[c00 + 1];
            float p02 = __expf(ae[j0][2] - cmv[c00]) * civ[c00];
            float p03 = __expf(ae[j0][3] - cmv[c00 + 1]) * civ[c00 + 1];
            float p10 = __expf(ae[j1][0] - cmv[c10]) * civ[c10];
            float p11 = __expf(ae[j1][1] - cmv[c10 + 1]) * civ[c10 + 1];
            float p12 = __expf(ae[j1][2] - cmv[c10]) * civ[c10];
            float p13 = __expf(ae[j1][3] - cmv[c10 + 1]) * civ[c10 + 1];
            a2[s][0] = bf2u(p00, p01);
            a2[s][1] = bf2u(p02, p03);
            a2[s][2] = bf2u(p10, p11);
            a2[s][3] = bf2u(p12, p13);
        }

        // PV-MMA: N=144 (18 frags), K=64 (4 k-steps via 2 x4 loads)
#pragma unroll
        for (int j2 = 0; j2 < 18; j2++) {
#pragma unroll
            for (int kp = 0; kp < 2; kp++) {
                uint32_t bb[4];
                ldsm_x4(bb, vb + (8 * j2 + (l & 7)) * (VSS * 2) + kp * 64 +
                                ((l >> 3) & 1) * 16 + (l >> 4) * 32);
                mma16816(acc2[j2], a2[2 * kp], bb[0], bb[1]);
                mma16816(acc2[j2], a2[2 * kp + 1], bb[2], bb[3]);
            }
        }
    }
    __syncthreads();

    if (tig == 0) {                       // col 128 (frag 16, pos 0) = rowsum(P)
        rsum[16 * w + g] = acc2[16][0];
        rsum[16 * w + g + 8] = acc2[16][2];
    }
    __syncthreads();

    const int row = 16 * w + g;
    const float inv0 = 1.0f / (1e-9f + rsum[row]);
    const float inv1 = 1.0f / (1e-9f + rsum[row + 8]);
    float* dst0 = &g_xr[((size_t)b * NPTS + n0 + row) * CIN];
    float* dst1 = &g_xr[((size_t)b * NPTS + n0 + row + 8) * CIN];
#pragma unroll
    for (int j2 = 0; j2 < 16; j2++) {
        int col = 8 * j2 + 2 * tig;
        *(float2*)&dst0[col] = make_float2(acc2[j2][0] * inv0, acc2[j2][1] * inv0);
        *(float2*)&dst1[col] = make_float2(acc2[j2][2] * inv1, acc2[j2][3] * inv1);
    }
}

// ---------------- K4: y = leaky(BN((x - xr) @ Wp^T)) + x via mma.sync ----------------
__global__ __launch_bounds__(256) void k_proj_mma(const float* __restrict__ x,
                                                  const float* __restrict__ gamma,
                                                  const float* __restrict__ beta,
                                                  const float* __restrict__ mean,
                                                  const float* __restrict__ var,
                                                  float* __restrict__ out) {
    __shared__ __nv_bfloat16 Ds[64 * XS];
    __shared__ __nv_bfloat16 Ws[64 * XS];
    const int tid = threadIdx.x, w = tid >> 5, l = tid & 31;
    const int r0 = blockIdx.x * 64;
    const int c0 = blockIdx.y * 64;
    const int wn = w & 3, wc = w >> 2;

#pragma unroll
    for (int i = tid; i < 4096; i += 256) {
        int row = i >> 6, cp = i & 63;
        float2 xv = *(const float2*)&x[(size_t)(r0 + row) * CIN + cp * 2];
        float2 rv = *(const float2*)&g_xr[(size_t)(r0 + row) * CIN + cp * 2];
        *(uint32_t*)&Ds[row * XS + cp * 2] = bf2u(xv.x - rv.x, xv.y - rv.y);
        *(uint32_t*)&Ws[row * XS + cp * 2] = *(const uint32_t*)&g_wph[(c0 + row) * CIN + cp * 2];
    }
    __syncthreads();

    const uint32_t db = smem_u32(Ds), wb = smem_u32(Ws);
    float acc[4][4] = {};
#pragma unroll
    for (int kp = 0; kp < 4; kp++) {
        uint32_t a[2][4];
        ldsm_x4(a[0], db + (16 * wn + (l & 15)) * (XS * 2) + (2 * kp) * 32 + (l >> 4) * 16);
        ldsm_x4(a[1], db + (16 * wn + (l & 15)) * (XS * 2) + (2 * kp + 1) * 32 + (l >> 4) * 16);
#pragma unroll
        for (int j = 0; j < 4; j++) {
            uint32_t bb[4];
            ldsm_x4(bb, wb + (32 * wc + 8 * j + (l & 7)) * (XS * 2) + kp * 64 +
                            ((l >> 3) & 1) * 16 + (l >> 4) * 32);
            mma16816(acc[j], a[0], bb[0], bb[1]);
            mma16816(acc[j], a[1], bb[2], bb[3]);
        }
    }

    const int g = l >> 2, tig = l & 3;
#pragma unroll
    for (int j = 0; j < 4; j++) {
        int o = c0 + 32 * wc + 8 * j + 2 * tig;
        float sc0 = gamma[o] * rsqrtf(var[o] + 1e-5f);
        float sc1 = gamma[o + 1] * rsqrtf(var[o + 1] + 1e-5f);
        float b0 = beta[o], b1 = beta[o + 1];
        float m0 = mean[o], m1 = mean[o + 1];
#pragma unroll
        for (int h = 0; h < 2; h++) {
            int r = r0 + 16 * wn + g + h * 8;
            float2 xv = *(const float2*)&x[(size_t)r * CIN + o];
            float y0 = (acc[j][h * 2] - m0) * sc0 + b0;
            float y1 = (acc[j][h * 2 + 1] - m1) * sc1 + b1;
            y0 = (y0 >= 0.f) ? y0 : 0.01f * y0;
            y1 = (y1 >= 0.f) ? y1 : 0.01f * y1;
            *(float2*)&out[(size_t)r * CIN + o] = make_float2(y0 + xv.x, y1 + xv.y);
        }
    }
}

// ---------------- launch ----------------
extern "C" void kernel_launch(void* const* d_in, const int* in_sizes, int n_in,
                              void* d_out, int out_size) {
    const float* x     = (const float*)d_in[0];
    const float* Wq    = (const float*)d_in[1];
    const float* Wk    = (const float*)d_in[2];
    const float* Wv    = (const float*)d_in[3];
    const float* Wp    = (const float*)d_in[4];
    const float* gamma = (const float*)d_in[5];
    const float* beta  = (const float*)d_in[6];
    const float* mean  = (const float*)d_in[7];
    const float* var   = (const float*)d_in[8];
    float* out = (float*)d_out;

    k_wconv<<<160, 256>>>(Wq, Wk, Wv, Wp);
    k_qkv_mma<<<dim3((BATCH * NPTS) / 64, 3), 256>>>(x);
    k_init_ones<<<(BATCH * 16 * NPTS) / 256, 256>>>();
    k_stats<<<dim3(NPTS / 128, BATCH), 256>>>();
    k_xr_mma<<<dim3(NPTS / 128, BATCH), 256>>>();
    k_proj_mma<<<dim3((BATCH * NPTS) / 64, 2), 256>>>(x, gamma, beta, mean, var, out);
}